// round 1
// baseline (speedup 1.0000x reference)
#include <cuda_runtime.h>
#include <cuda_bf16.h>

#define MARGIN   0.1f
#define BEPS     1e-5f
#define AEPS     1e-7f

#define MAXB 4608
#define MAXC 10240

// scratch (no allocations allowed in kernel_launch)
static __device__ double g_hsum;
static __device__ float  g_pn[MAXB];     // clipped ||pred||^2
static __device__ float  g_cb[MAXB];     // 2/(1-pn)
static __device__ float  g_scorr[MAXB];  // dist2correct + MARGIN
static __device__ float  g_an[MAXC];     // clipped ||all||^2
static __device__ float  g_ca[MAXC];     // 1/(1-an)

__global__ void prep_kernel(const float* __restrict__ pred,
                            const float* __restrict__ tgt,
                            const float* __restrict__ all,
                            int B, int C) {
    int i = blockIdx.x * blockDim.x + threadIdx.x;
    if (i == 0) g_hsum = 0.0;

    if (i < C) {
        const float4* a4 = (const float4*)(all + (size_t)i * 64);
        float s = 0.f;
#pragma unroll
        for (int j = 0; j < 16; j++) {
            float4 v = a4[j];
            s = fmaf(v.x, v.x, s); s = fmaf(v.y, v.y, s);
            s = fmaf(v.z, v.z, s); s = fmaf(v.w, v.w, s);
        }
        s = fminf(fmaxf(s, 0.f), 1.0f - BEPS);
        g_an[i] = s;
        g_ca[i] = 1.0f / (1.0f - s);
    }

    if (i < B) {
        const float4* p4 = (const float4*)(pred + (size_t)i * 64);
        const float4* t4 = (const float4*)(tgt  + (size_t)i * 64);
        float pn = 0.f, tn = 0.f, sq = 0.f;
#pragma unroll
        for (int j = 0; j < 16; j++) {
            float4 p = p4[j];
            float4 t = t4[j];
            pn = fmaf(p.x, p.x, pn); pn = fmaf(p.y, p.y, pn);
            pn = fmaf(p.z, p.z, pn); pn = fmaf(p.w, p.w, pn);
            tn = fmaf(t.x, t.x, tn); tn = fmaf(t.y, t.y, tn);
            tn = fmaf(t.z, t.z, tn); tn = fmaf(t.w, t.w, tn);
            float dx = p.x - t.x, dy = p.y - t.y, dz = p.z - t.z, dw = p.w - t.w;
            sq = fmaf(dx, dx, sq); sq = fmaf(dy, dy, sq);
            sq = fmaf(dz, dz, sq); sq = fmaf(dw, dw, sq);
        }
        pn = fminf(fmaxf(pn, 0.f), 1.0f - BEPS);
        tn = fminf(fmaxf(tn, 0.f), 1.0f - BEPS);
        float x = 1.0f + 2.0f * sq / ((1.0f - pn) * (1.0f - tn));
        x = fmaxf(x, 1.0f + AEPS);
        float d2c = logf(x + sqrtf(x * x - 1.0f));
        g_pn[i]    = pn;
        g_cb[i]    = 2.0f / (1.0f - pn);
        g_scorr[i] = d2c + MARGIN;
    }
}

// 64x64 tile, 256 threads, 4x4 micro-tile, K=64 resident in smem.
#define BM 64
#define BN 64
#define SPAD 68   // 68*4 = 272 bytes/row, 16B aligned

__global__ __launch_bounds__(256)
void poincare_main_kernel(const float* __restrict__ pred,
                          const float* __restrict__ all,
                          int B, int C) {
    __shared__ float As[64][SPAD];   // [k][m]
    __shared__ float Bs[64][SPAD];   // [k][n]
    __shared__ float red[256];

    const int tid = threadIdx.x;
    const int bm  = blockIdx.y * BM;
    const int bn  = blockIdx.x * BN;

    // Load tiles: 64 rows x 64 k each = 1024 float4 each; 4 per thread.
#pragma unroll
    for (int i = 0; i < 4; i++) {
        int idx = tid + i * 256;          // 0..1023
        int row = idx >> 4;               // 0..63
        int kq  = idx & 15;               // float4 index along k

        float4 v = make_float4(0.f, 0.f, 0.f, 0.f);
        int m = bm + row;
        if (m < B) v = ((const float4*)pred)[(size_t)m * 16 + kq];
        As[kq * 4 + 0][row] = v.x;
        As[kq * 4 + 1][row] = v.y;
        As[kq * 4 + 2][row] = v.z;
        As[kq * 4 + 3][row] = v.w;

        float4 w = make_float4(0.f, 0.f, 0.f, 0.f);
        int c = bn + row;
        if (c < C) w = ((const float4*)all)[(size_t)c * 16 + kq];
        Bs[kq * 4 + 0][row] = w.x;
        Bs[kq * 4 + 1][row] = w.y;
        Bs[kq * 4 + 2][row] = w.z;
        Bs[kq * 4 + 3][row] = w.w;
    }
    __syncthreads();

    const int tx = tid & 15;   // n-dim: 16 threads * 4
    const int ty = tid >> 4;   // m-dim: 16 threads * 4

    float acc[4][4] = {};

#pragma unroll 16
    for (int k = 0; k < 64; k++) {
        float4 a = *(const float4*)&As[k][ty * 4];
        float4 b = *(const float4*)&Bs[k][tx * 4];
        acc[0][0] = fmaf(a.x, b.x, acc[0][0]);
        acc[0][1] = fmaf(a.x, b.y, acc[0][1]);
        acc[0][2] = fmaf(a.x, b.z, acc[0][2]);
        acc[0][3] = fmaf(a.x, b.w, acc[0][3]);
        acc[1][0] = fmaf(a.y, b.x, acc[1][0]);
        acc[1][1] = fmaf(a.y, b.y, acc[1][1]);
        acc[1][2] = fmaf(a.y, b.z, acc[1][2]);
        acc[1][3] = fmaf(a.y, b.w, acc[1][3]);
        acc[2][0] = fmaf(a.z, b.x, acc[2][0]);
        acc[2][1] = fmaf(a.z, b.y, acc[2][1]);
        acc[2][2] = fmaf(a.z, b.z, acc[2][2]);
        acc[2][3] = fmaf(a.z, b.w, acc[2][3]);
        acc[3][0] = fmaf(a.w, b.x, acc[3][0]);
        acc[3][1] = fmaf(a.w, b.y, acc[3][1]);
        acc[3][2] = fmaf(a.w, b.z, acc[3][2]);
        acc[3][3] = fmaf(a.w, b.w, acc[3][3]);
    }

    // Fused epilogue: arccosh distance + hinge, accumulate per-thread.
    float pnv[4], cbv[4], scv[4];
    bool  mv[4];
#pragma unroll
    for (int i = 0; i < 4; i++) {
        int m = bm + ty * 4 + i;
        mv[i] = (m < B);
        int mc = mv[i] ? m : 0;
        pnv[i] = g_pn[mc];
        cbv[i] = g_cb[mc];
        scv[i] = g_scorr[mc];
    }
    float anv[4], cav[4];
    bool  cv[4];
#pragma unroll
    for (int j = 0; j < 4; j++) {
        int c = bn + tx * 4 + j;
        cv[j] = (c < C);
        int cc = cv[j] ? c : 0;
        anv[j] = g_an[cc];
        cav[j] = g_ca[cc];
    }

    float acc_h = 0.f;
#pragma unroll
    for (int i = 0; i < 4; i++) {
#pragma unroll
        for (int j = 0; j < 4; j++) {
            if (mv[i] && cv[j]) {
                float sqd = fmaxf(pnv[i] + anv[j] - 2.0f * acc[i][j], 0.f);
                float x   = fmaf(sqd, cbv[i] * cav[j], 1.0f);
                x = fmaxf(x, 1.0f + AEPS);
                float d = __logf(x + __fsqrt_rn(fmaf(x, x, -1.0f)));
                acc_h += fmaxf(scv[i] - d, 0.f);
            }
        }
    }

    // Block reduction
    red[tid] = acc_h;
    __syncthreads();
#pragma unroll
    for (int s = 128; s > 0; s >>= 1) {
        if (tid < s) red[tid] += red[tid + s];
        __syncthreads();
    }
    if (tid == 0) atomicAdd(&g_hsum, (double)red[0]);
}

__global__ void finalize_kernel(float* out, int B) {
    double h = g_hsum;
    out[0] = (float)((h - 0.1 * (double)B) / (double)B);
}

extern "C" void kernel_launch(void* const* d_in, const int* in_sizes, int n_in,
                              void* d_out, int out_size) {
    const float* pred = (const float*)d_in[0];
    const float* tgt  = (const float*)d_in[1];
    const float* all  = (const float*)d_in[2];
    float* out = (float*)d_out;

    int B = in_sizes[0] / 64;
    int C = in_sizes[2] / 64;

    int n = (B > C) ? B : C;
    prep_kernel<<<(n + 255) / 256, 256>>>(pred, tgt, all, B, C);

    dim3 grid((C + BN - 1) / BN, (B + BM - 1) / BM);
    poincare_main_kernel<<<grid, 256>>>(pred, all, B, C);

    finalize_kernel<<<1, 1>>>(out, B);
}

// round 2
// speedup vs baseline: 1.2759x; 1.2759x over previous
#include <cuda_runtime.h>
#include <cuda_bf16.h>

#define MARGIN   0.1f
#define BEPS     1e-5f
#define AEPS     1e-7f

#define MAXB 4608
#define MAXC 10240

static __device__ double g_hsum;
static __device__ float  g_pn[MAXB];     // clipped ||pred||^2
static __device__ float  g_cb[MAXB];     // 2/(1-pn)
static __device__ float  g_scorr[MAXB];  // dist2correct + MARGIN
static __device__ float  g_an[MAXC];     // clipped ||all||^2
static __device__ float  g_ca[MAXC];     // 1/(1-an)

// ---------------- prep: 4 threads per row, shfl-reduced ----------------
__global__ void prep_kernel(const float* __restrict__ pred,
                            const float* __restrict__ tgt,
                            const float* __restrict__ all,
                            int B, int C) {
    int gid  = blockIdx.x * blockDim.x + threadIdx.x;
    int r    = gid >> 2;
    int lane = gid & 3;
    if (gid == 0) g_hsum = 0.0;

    if (r < C) {
        const float4* a4 = (const float4*)(all + (size_t)r * 64) + lane * 4;
        float s = 0.f;
#pragma unroll
        for (int j = 0; j < 4; j++) {
            float4 v = a4[j];
            s = fmaf(v.x, v.x, s); s = fmaf(v.y, v.y, s);
            s = fmaf(v.z, v.z, s); s = fmaf(v.w, v.w, s);
        }
        s += __shfl_xor_sync(0xFFFFFFFFu, s, 1);
        s += __shfl_xor_sync(0xFFFFFFFFu, s, 2);
        if (lane == 0) {
            s = fminf(fmaxf(s, 0.f), 1.0f - BEPS);
            g_an[r] = s;
            g_ca[r] = 1.0f / (1.0f - s);
        }
    }

    if (r < B) {
        const float4* p4 = (const float4*)(pred + (size_t)r * 64) + lane * 4;
        const float4* t4 = (const float4*)(tgt  + (size_t)r * 64) + lane * 4;
        float pn = 0.f, tn = 0.f, sq = 0.f;
#pragma unroll
        for (int j = 0; j < 4; j++) {
            float4 p = p4[j];
            float4 t = t4[j];
            pn = fmaf(p.x, p.x, pn); pn = fmaf(p.y, p.y, pn);
            pn = fmaf(p.z, p.z, pn); pn = fmaf(p.w, p.w, pn);
            tn = fmaf(t.x, t.x, tn); tn = fmaf(t.y, t.y, tn);
            tn = fmaf(t.z, t.z, tn); tn = fmaf(t.w, t.w, tn);
            float dx = p.x - t.x, dy = p.y - t.y, dz = p.z - t.z, dw = p.w - t.w;
            sq = fmaf(dx, dx, sq); sq = fmaf(dy, dy, sq);
            sq = fmaf(dz, dz, sq); sq = fmaf(dw, dw, sq);
        }
        pn += __shfl_xor_sync(0xFFFFFFFFu, pn, 1);
        pn += __shfl_xor_sync(0xFFFFFFFFu, pn, 2);
        tn += __shfl_xor_sync(0xFFFFFFFFu, tn, 1);
        tn += __shfl_xor_sync(0xFFFFFFFFu, tn, 2);
        sq += __shfl_xor_sync(0xFFFFFFFFu, sq, 1);
        sq += __shfl_xor_sync(0xFFFFFFFFu, sq, 2);
        if (lane == 0) {
            pn = fminf(fmaxf(pn, 0.f), 1.0f - BEPS);
            tn = fminf(fmaxf(tn, 0.f), 1.0f - BEPS);
            float x = 1.0f + 2.0f * sq / ((1.0f - pn) * (1.0f - tn));
            x = fmaxf(x, 1.0f + AEPS);
            float d2c = logf(x + sqrtf(x * x - 1.0f));
            g_pn[r]    = pn;
            g_cb[r]    = 2.0f / (1.0f - pn);
            g_scorr[r] = d2c + MARGIN;
        }
    }
}

// ---------------- main: 64x64 tile, 256 threads, 4x4 micro, f32x2 FMA ----------------
#define BM 64
#define BN 64

__device__ __forceinline__ unsigned long long pack_dup(float v) {
    unsigned long long r;
    asm("mov.b64 %0, {%1, %1};" : "=l"(r) : "f"(v));
    return r;
}
__device__ __forceinline__ void ffma2(unsigned long long& d, unsigned long long a,
                                      unsigned long long b) {
    asm("fma.rn.f32x2 %0, %1, %2, %0;" : "+l"(d) : "l"(a), "l"(b));
}
__device__ __forceinline__ void unpack2(unsigned long long v, float& lo, float& hi) {
    asm("mov.b64 {%0, %1}, %2;" : "=f"(lo), "=f"(hi) : "l"(v));
}

__global__ __launch_bounds__(256)
void poincare_main_kernel(const float* __restrict__ pred,
                          const float* __restrict__ all,
                          int B, int C) {
    // [k][m] layout, 64 floats per row, XOR-swizzled quads: phys_quad = quad ^ (kq & 7)
    __shared__ float As[64 * 64];
    __shared__ float Bs[64 * 64];
    __shared__ float red[256];

    const int tid = threadIdx.x;
    const int bm  = blockIdx.y * BM;
    const int bn  = blockIdx.x * BN;

    // Load tiles: 1024 float4 per tile, 4 per thread. Swizzled transpose store.
#pragma unroll
    for (int i = 0; i < 4; i++) {
        int idx = tid + i * 256;      // 0..1023
        int row = idx >> 4;           // 0..63 (m or n)
        int kq  = idx & 15;           // float4 index along k

        // swizzled scalar column position (same for all 4 k's of this float4)
        int col = (((row >> 2) ^ (kq & 7)) << 2) | (row & 3);
        int kb  = (kq << 2) * 64;     // k = 4*kq + c, row stride 64

        float4 v = make_float4(0.f, 0.f, 0.f, 0.f);
        int m = bm + row;
        if (m < B) v = ((const float4*)pred)[(size_t)m * 16 + kq];
        As[kb         + col] = v.x;
        As[kb + 64    + col] = v.y;
        As[kb + 128   + col] = v.z;
        As[kb + 192   + col] = v.w;

        float4 w = make_float4(0.f, 0.f, 0.f, 0.f);
        int c = bn + row;
        if (c < C) w = ((const float4*)all)[(size_t)c * 16 + kq];
        Bs[kb         + col] = w.x;
        Bs[kb + 64    + col] = w.y;
        Bs[kb + 128   + col] = w.z;
        Bs[kb + 192   + col] = w.w;
    }
    __syncthreads();

    const int tx = tid & 15;   // n: 16 threads * 4
    const int ty = tid >> 4;   // m: 16 threads * 4

    unsigned long long acc2[4][2] = {};  // [i][j-pair], f32x2 packed

    const float4*     As4 = (const float4*)As;
    const ulonglong2* Bs2 = (const ulonglong2*)Bs;

#pragma unroll 16
    for (int k = 0; k < 64; k++) {
        int sw = (k >> 2) & 7;
        float4 a = As4[k * 16 + (ty ^ sw)];
        ulonglong2 bp = Bs2[k * 16 + (tx ^ sw)];   // (b0,b1),(b2,b3)

        unsigned long long a0 = pack_dup(a.x);
        unsigned long long a1 = pack_dup(a.y);
        unsigned long long a2 = pack_dup(a.z);
        unsigned long long a3 = pack_dup(a.w);

        ffma2(acc2[0][0], a0, bp.x); ffma2(acc2[0][1], a0, bp.y);
        ffma2(acc2[1][0], a1, bp.x); ffma2(acc2[1][1], a1, bp.y);
        ffma2(acc2[2][0], a2, bp.x); ffma2(acc2[2][1], a2, bp.y);
        ffma2(acc2[3][0], a3, bp.x); ffma2(acc2[3][1], a3, bp.y);
    }

    // unpack accumulators
    float acc[4][4];
#pragma unroll
    for (int i = 0; i < 4; i++) {
        unpack2(acc2[i][0], acc[i][0], acc[i][1]);
        unpack2(acc2[i][1], acc[i][2], acc[i][3]);
    }

    // Fused epilogue
    float pnv[4], cbv[4], scv[4];
    bool  mv[4];
#pragma unroll
    for (int i = 0; i < 4; i++) {
        int m = bm + ty * 4 + i;
        mv[i] = (m < B);
        int mc = mv[i] ? m : 0;
        pnv[i] = g_pn[mc];
        cbv[i] = g_cb[mc];
        scv[i] = g_scorr[mc];
    }
    float anv[4], cav[4];
    bool  cv[4];
#pragma unroll
    for (int j = 0; j < 4; j++) {
        int c = bn + tx * 4 + j;
        cv[j] = (c < C);
        int cc = cv[j] ? c : 0;
        anv[j] = g_an[cc];
        cav[j] = g_ca[cc];
    }

    float acc_h = 0.f;
#pragma unroll
    for (int i = 0; i < 4; i++) {
#pragma unroll
        for (int j = 0; j < 4; j++) {
            if (mv[i] && cv[j]) {
                float sqd = fmaxf(pnv[i] + anv[j] - 2.0f * acc[i][j], 0.f);
                float x   = fmaf(sqd, cbv[i] * cav[j], 1.0f);
                x = fmaxf(x, 1.0f + AEPS);
                float d = __logf(x + __fsqrt_rn(fmaf(x, x, -1.0f)));
                acc_h += fmaxf(scv[i] - d, 0.f);
            }
        }
    }

    // Block reduction
    red[tid] = acc_h;
    __syncthreads();
#pragma unroll
    for (int s = 128; s > 0; s >>= 1) {
        if (tid < s) red[tid] += red[tid + s];
        __syncthreads();
    }
    if (tid == 0) atomicAdd(&g_hsum, (double)red[0]);
}

__global__ void finalize_kernel(float* out, int B) {
    double h = g_hsum;
    out[0] = (float)((h - 0.1 * (double)B) / (double)B);
}

extern "C" void kernel_launch(void* const* d_in, const int* in_sizes, int n_in,
                              void* d_out, int out_size) {
    const float* pred = (const float*)d_in[0];
    const float* tgt  = (const float*)d_in[1];
    const float* all  = (const float*)d_in[2];
    float* out = (float*)d_out;

    int B = in_sizes[0] / 64;
    int C = in_sizes[2] / 64;

    int nthr = ((B > C) ? B : C) * 4;
    prep_kernel<<<(nthr + 255) / 256, 256>>>(pred, tgt, all, B, C);

    dim3 grid((C + BN - 1) / BN, (B + BM - 1) / BM);
    poincare_main_kernel<<<grid, 256>>>(pred, all, B, C);

    finalize_kernel<<<1, 1>>>(out, B);
}